// round 9
// baseline (speedup 1.0000x reference)
#include <cuda_runtime.h>
#include <cuda_fp16.h>
#include <cstdint>
#include <cstddef>

#define T_TOK 8192
#define HDIM  1536
#define I2    6144
#define IH    3072
#define ALPHA 1.702f
#define LIMIT 7.0f
#define NSTG  4
#define STGB  49152
#define SMEMSZ (NSTG * STGB + 1024)   // +1KB so we can align the base to 1024

// tiled + SW128-swizzled fp16 operand storage (K-major, 64-half K-blocks)
__device__ __align__(1024) __half g_xn [(size_t)T_TOK * HDIM];
__device__ __align__(1024) __half g_act[(size_t)T_TOK * IH * 4];
__device__ __align__(1024) __half g_wu [(size_t)4 * I2 * HDIM];
__device__ __align__(1024) __half g_wd [(size_t)4 * HDIM * IH];
__device__ float g_probs[T_TOK * 4];
__device__ float g_bu[4 * I2];
__device__ float g_bd[4 * HDIM];
__device__ int   g_eids[4];

__device__ __forceinline__ uint32_t smem_u32(const void* p) {
    uint32_t a;
    asm("{ .reg .u64 t; cvta.to.shared.u64 t, %1; cvt.u32.u64 %0, t; }" : "=r"(a) : "l"(p));
    return a;
}
__device__ __forceinline__ uint32_t h2u(__half2 h) {
    union { __half2 h; uint32_t u; } c; c.h = h; return c.u;
}

#define MBAR_INIT(a, c) \
    asm volatile("mbarrier.init.shared.b64 [%0], %1;" :: "r"((uint32_t)(a)), "r"((uint32_t)(c)) : "memory")
#define MBAR_EXPECT(a, b) \
    asm volatile("mbarrier.arrive.expect_tx.shared.b64 _, [%0], %1;" :: "r"((uint32_t)(a)), "r"((uint32_t)(b)) : "memory")
#define MBAR_ARRIVE(a) \
    asm volatile("mbarrier.arrive.shared.b64 _, [%0];" :: "r"((uint32_t)(a)) : "memory")
#define MBAR_WAIT(a, p) do { \
    uint32_t _m = (uint32_t)(a), _p = (uint32_t)(p), _d; \
    asm volatile("{\n\t.reg .pred q;\n\t" \
        "mbarrier.try_wait.parity.acquire.cta.shared::cta.b64 q, [%1], %2;\n\t" \
        "selp.b32 %0, 1, 0, q;\n\t}" : "=r"(_d) : "r"(_m), "r"(_p) : "memory"); \
    if (!_d) { \
        asm volatile("{\n\t.reg .pred Q;\n\tL%=:\n\t" \
            "mbarrier.try_wait.parity.acquire.cta.shared::cta.b64 Q, [%0], %1, 0x989680;\n\t" \
            "@Q bra.uni D%=;\n\tbra.uni L%=;\n\tD%=:\n\t}" \
            :: "r"(_m), "r"(_p) : "memory"); \
    } \
} while (0)
#define BULK(sdst, gsrc, sz, mbar) \
    asm volatile("cp.async.bulk.shared::cluster.global.mbarrier::complete_tx::bytes " \
                 "[%0], [%1], %2, [%3];" \
                 :: "r"((uint32_t)(sdst)), "l"(gsrc), "r"((uint32_t)(sz)), "r"((uint32_t)(mbar)) : "memory")
#define LDSM4(a0,a1,a2,a3,addr) \
    asm volatile("ldmatrix.sync.aligned.m8n8.x4.shared.b16 {%0,%1,%2,%3}, [%4];" \
        : "=r"(a0),"=r"(a1),"=r"(a2),"=r"(a3) : "r"(addr))
#define MMA(c,a,b) \
    asm volatile("mma.sync.aligned.m16n8k16.row.col.f32.f16.f16.f32 " \
        "{%0,%1,%2,%3},{%4,%5,%6,%7},{%8,%9},{%0,%1,%2,%3};" \
        : "+f"((c)[0]),"+f"((c)[1]),"+f"((c)[2]),"+f"((c)[3]) \
        : "r"((a)[0]),"r"((a)[1]),"r"((a)[2]),"r"((a)[3]),"r"((b)[0]),"r"((b)[1]))

// fragment prefetch: swizzle XOR applied to the OFFSET (carry-free, bits 5-6),
// then added to the 1024-aligned stage base — exact regardless of smem layout.
#define LDFRAG(BUF, KS) do { \
    _Pragma("unroll") \
    for (int _i = 0; _i < 4; ++_i) \
        LDSM4(af[BUF][_i][0],af[BUF][_i][1],af[BUF][_i][2],af[BUF][_i][3], \
              sA + (baseA[_i] ^ ((KS) << 5))); \
    _Pragma("unroll") \
    for (int _j = 0; _j < 4; ++_j) \
        LDSM4(bf[BUF][2*_j][0],bf[BUF][2*_j][1],bf[BUF][2*_j+1][0],bf[BUF][2*_j+1][1], \
              sA + (baseB[_j] ^ ((KS) << 5))); \
} while (0)

// ------- prep: RMSNorm -> g_xn (tiled fp16) + out=x + router (fused) --------
__global__ void moe_prep(const float* __restrict__ x, const float* __restrict__ ns,
                         const float* __restrict__ gw, float* __restrict__ out) {
    int t = blockIdx.x, tid = threadIdx.x, lane = tid & 31, w = tid >> 5;  // 128 thr
    __shared__ float4 sxn[HDIM / 4];
    __shared__ float sred[4], slog[16];
    const float4* xr = (const float4*)(x + (size_t)t * HDIM);
    float4 v[3]; float ss = 0.f;
#pragma unroll
    for (int i = 0; i < 3; ++i) {
        v[i] = xr[tid + i * 128];
        ss += v[i].x*v[i].x + v[i].y*v[i].y + v[i].z*v[i].z + v[i].w*v[i].w;
    }
#pragma unroll
    for (int o = 16; o; o >>= 1) ss += __shfl_xor_sync(0xFFFFFFFFu, ss, o);
    if (lane == 0) sred[w] = ss;
    __syncthreads();
    float rs = rsqrtf((sred[0]+sred[1]+sred[2]+sred[3]) / (float)HDIM + 1e-6f);
    float4* outr = (float4*)(out + (size_t)t * HDIM);
    const float4* sc = (const float4*)ns;
    int mb = t >> 7, r = t & 127;
#pragma unroll
    for (int i = 0; i < 3; ++i) {
        int idx = tid + i * 128;
        float4 s4 = sc[idx], xv = v[i];
        outr[idx] = xv;
        float4 xn = make_float4(xv.x*rs*s4.x, xv.y*rs*s4.y, xv.z*rs*s4.z, xv.w*rs*s4.w);
        sxn[idx] = xn;
        int k0 = idx * 4, kb = k0 >> 6, c8 = (k0 & 63) >> 3;
        __half* dst = g_xn + ((size_t)(mb*24 + kb))*8192 + r*64 + ((c8 ^ (r & 7)) * 8) + (k0 & 7);
        *(uint2*)dst = make_uint2(h2u(__floats2half2_rn(xn.x, xn.y)),
                                  h2u(__floats2half2_rn(xn.z, xn.w)));
    }
    __syncthreads();
#pragma unroll
    for (int e = 0; e < 4; ++e) {
        const float4* ge = (const float4*)(gw + (size_t)(4*w + e) * HDIM);
        float d = 0.f;
#pragma unroll
        for (int i = 0; i < 12; ++i) {
            int idx = lane + i * 32;
            float4 a = sxn[idx], b = ge[idx];
            d += a.x*b.x + a.y*b.y + a.z*b.z + a.w*b.w;
        }
#pragma unroll
        for (int o = 16; o; o >>= 1) d += __shfl_xor_sync(0xFFFFFFFFu, d, o);
        if (lane == 0) slog[4*w + e] = d;
    }
    __syncthreads();
    if (tid == 0) {
        float vv[16]; unsigned used = 0; float tv[4]; int ti[4];
#pragma unroll
        for (int e = 0; e < 16; ++e) vv[e] = slog[e];
#pragma unroll
        for (int i = 0; i < 4; ++i) {
            float best = -1e30f; int bi = 0;
#pragma unroll
            for (int e = 0; e < 16; ++e)
                if (!((used>>e)&1u) && vv[e] > best) { best = vv[e]; bi = e; }
            used |= 1u << bi; tv[i] = best; ti[i] = bi;
        }
        float mx = tv[0], sum = 0.f, pr[4];
#pragma unroll
        for (int i = 0; i < 4; ++i) { pr[i] = expf(tv[i]-mx); sum += pr[i]; }
#pragma unroll
        for (int i = 0; i < 4; ++i) g_probs[t*4+i] = pr[i] / sum;
        if (t == 0) { for (int i = 0; i < 4; ++i) g_eids[i] = ti[i]; }
    }
}

// -------- convert: gather 4 experts, fp32->fp16, retile + swizzle ------------
__global__ void moe_convert(const float* __restrict__ wu, const float* __restrict__ wd,
                            const float* __restrict__ bu, const float* __restrict__ bd) {
    const int NU = I2*HDIM/8, ND = HDIM*IH/8, PER = NU + ND;
    const long long total = 4ll * PER;
    long long stride = (long long)gridDim.x * blockDim.x;
    for (long long i = (long long)blockIdx.x*blockDim.x + threadIdx.x; i < total; i += stride) {
        int slot = (int)(i / PER), r = (int)(i - (long long)slot * PER);
        int eid = g_eids[slot];
        const float4* src; __half* dst;
        if (r < NU) {
            int row = r / 192, k0 = (r % 192) * 8;
            src = (const float4*)(wu + (size_t)eid*I2*HDIM + (size_t)row*HDIM + k0);
            int lin = row >= IH, a = lin ? row - IH : row;
            int nb = slot*24 + (a >> 7), ar = a & 127;
            int rr = (ar >> 3) * 16 + (lin ? 8 : 0) + (ar & 7);
            int kb = k0 >> 6, c8 = (k0 & 63) >> 3;
            dst = g_wu + ((size_t)(nb*24 + kb))*16384 + rr*64 + ((c8 ^ (rr & 7)) * 8);
        } else {
            int r2 = r - NU;
            int row = r2 / 384, k0 = (r2 % 384) * 8;
            src = (const float4*)(wd + (size_t)eid*HDIM*IH + (size_t)row*IH + k0);
            int nb = row >> 8, rr = row & 255;
            int kbg = slot*48 + (k0 >> 6), c8 = (k0 & 63) >> 3;
            dst = g_wd + ((size_t)(nb*192 + kbg))*16384 + rr*64 + ((c8 ^ (rr & 7)) * 8);
        }
        float4 a = src[0], b = src[1];
        *(uint4*)dst = make_uint4(h2u(__floats2half2_rn(a.x,a.y)), h2u(__floats2half2_rn(a.z,a.w)),
                                  h2u(__floats2half2_rn(b.x,b.y)), h2u(__floats2half2_rn(b.z,b.w)));
    }
    int gt = blockIdx.x*blockDim.x + threadIdx.x;
    if (gt < 4*(I2+HDIM)) {
        int slot = gt/(I2+HDIM), j = gt%(I2+HDIM), eid = g_eids[slot];
        if (j < I2) g_bu[slot*I2+j] = bu[(size_t)eid*I2 + j];
        else        g_bd[slot*HDIM + (j-I2)] = bd[(size_t)eid*HDIM + (j-I2)];
    }
}

// ------- persistent GEMM: 128x256 x K(64/stage), double-buffered frags ------
template <int KSTEPS, int EPI>
__global__ __launch_bounds__(288, 1) void gemm_tc(int ntiles, float* __restrict__ dout) {
    extern __shared__ char smem[];
    __shared__ __align__(8) unsigned long long mbar[2 * NSTG];
    uint32_t sb = (smem_u32(smem) + 1023u) & ~1023u;   // 1024-aligned stage base
    uint32_t mb0 = smem_u32(&mbar[0]);
    const int tid = threadIdx.x, lane = tid & 31, wid = tid >> 5;

    if (tid == 0) {
#pragma unroll
        for (int s = 0; s < NSTG; ++s) { MBAR_INIT(mb0 + 8*s, 1); MBAR_INIT(mb0 + 8*(NSTG+s), 8); }
        asm volatile("fence.proxy.async.shared::cta;" ::: "memory");
    }
    __syncthreads();

    if (wid == 8) {  // producer warp
        if (lane == 0) {
            int st = 0; uint32_t ph = 1;
            for (int tile = blockIdx.x; tile < ntiles; tile += gridDim.x) {
                int nb = tile >> 6, mb = tile & 63;
                const char* Ab = (const char*)(EPI ? g_act : g_xn) + (size_t)mb * KSTEPS * 16384;
                const char* Bb = (const char*)(EPI ? g_wd : g_wu) + (size_t)nb * KSTEPS * 32768;
                for (int s = 0; s < KSTEPS; ++s) {
                    MBAR_WAIT(mb0 + 8*(NSTG+st), ph);
                    MBAR_EXPECT(mb0 + 8*st, STGB - 1024 + 1024);  // 48KB
                    uint32_t sa = sb + st * STGB;
                    BULK(sa,         Ab + (size_t)s * 16384, 16384, mb0 + 8*st);
                    BULK(sa + 16384, Bb + (size_t)s * 32768, 32768, mb0 + 8*st);
                    if (++st == NSTG) { st = 0; ph ^= 1; }
                }
            }
        }
        return;
    }

    const int wm = (wid >> 2) * 64, wn = (wid & 3) * 64;
    const int lh = lane >> 4, grp = lane >> 3;
    uint32_t baseA[4], baseB[4];
#pragma unroll
    for (int i = 0; i < 4; ++i) {
        int ro = wm + i*16 + (lane & 15);
        baseA[i] = ro*128 + ((((ro & 7) ^ lh)) << 4);
    }
#pragma unroll
    for (int j = 0; j < 4; ++j) {
        int ro = wn + (2*j + (grp >> 1))*8 + (lane & 7);
        baseB[j] = 16384 + ro*128 + ((((ro & 7) ^ (grp & 1))) << 4);
    }

    int st = 0; uint32_t phF = 0;
    for (int tile = blockIdx.x; tile < ntiles; tile += gridDim.x) {
        int nb = tile >> 6, mb = tile & 63;
        float acc[4][8][4];
#pragma unroll
        for (int i = 0; i < 4; ++i)
#pragma unroll
            for (int j = 0; j < 8; ++j)
#pragma unroll
                for (int q = 0; q < 4; ++q) acc[i][j][q] = 0.f;

        uint32_t af[2][4][4], bf[2][8][2];
        MBAR_WAIT(mb0 + 8*st, phF);
        uint32_t sA = sb + st * STGB;
        LDFRAG(0, 0);

        for (int s = 0; s < KSTEPS; ++s) {
#pragma unroll
            for (int ks = 0; ks < 4; ++ks) {
                if (ks < 3) {
                    LDFRAG((ks + 1) & 1, ks + 1);
                } else {
                    if (lane == 0) MBAR_ARRIVE(mb0 + 8*(NSTG + st));
                    if (++st == NSTG) { st = 0; phF ^= 1; }
                    if (s + 1 < KSTEPS) {
                        MBAR_WAIT(mb0 + 8*st, phF);
                        sA = sb + st * STGB;
                        LDFRAG(0, 0);
                    }
                }
                const int buf = ks & 1;
#pragma unroll
                for (int i = 0; i < 4; ++i)
#pragma unroll
                    for (int j = 0; j < 8; ++j) MMA(acc[i][j], af[buf][i], bf[buf][j]);
            }
        }

        if (EPI == 0) {
            int slot = nb / 24, nbl = nb - slot * 24;
            const float* bug = g_bu + slot*I2 + nbl*128;
            const float* bul = bug + IH;
#pragma unroll
            for (int i = 0; i < 4; ++i) {
                int r = wm + i*16 + (lane >> 2);
                float p0 = g_probs[(mb*128 + r)*4 + slot];
                float p1 = g_probs[(mb*128 + r + 8)*4 + slot];
#pragma unroll
                for (int t = 0; t < 4; ++t) {
                    int ac = (wn >> 1) + t*8 + (lane & 3) * 2;
                    float bg0 = bug[ac], bg1 = bug[ac+1], bl0 = bul[ac], bl1 = bul[ac+1];
#pragma unroll
                    for (int h = 0; h < 2; ++h) {
                        int tr = r + h*8;
                        float pp = h ? p1 : p0;
                        float gg0 = acc[i][2*t][2*h]   + bg0, gg1 = acc[i][2*t][2*h+1]   + bg1;
                        float ll0 = acc[i][2*t+1][2*h] + bl0, ll1 = acc[i][2*t+1][2*h+1] + bl1;
                        gg0 = fminf(gg0, LIMIT); gg1 = fminf(gg1, LIMIT);
                        ll0 = fminf(fmaxf(ll0, -LIMIT), LIMIT);
                        ll1 = fminf(fmaxf(ll1, -LIMIT), LIMIT);
                        float a0 = pp * (gg0 / (1.f + __expf(-ALPHA*gg0)) * (ll0 + 1.f));
                        float a1 = pp * (gg1 / (1.f + __expf(-ALPHA*gg1)) * (ll1 + 1.f));
                        int ag = nb*128 + ac;
                        __half* dst = g_act + ((size_t)(mb*192 + (ag >> 6)))*8192
                            + tr*64 + ((((ag & 63) >> 3) ^ (tr & 7)) * 8) + (ac & 7);
                        *(__half2*)dst = __floats2half2_rn(a0, a1);
                    }
                }
            }
        } else {
#pragma unroll
            for (int i = 0; i < 4; ++i) {
                int r = wm + i*16 + (lane >> 2);
                int t0 = mb*128 + r;
                float4 P0 = *(const float4*)&g_probs[t0*4];
                float4 P1 = *(const float4*)&g_probs[(t0+8)*4];
                float* o0 = dout + (size_t)t0*HDIM + nb*256;
                float* o1 = o0 + 8ull*HDIM;
#pragma unroll
                for (int j = 0; j < 8; ++j) {
                    int c = wn + j*8 + (lane & 3) * 2;
                    int cg = nb*256 + c;
#pragma unroll
                    for (int q = 0; q < 2; ++q) {
                        float bd0 = g_bd[cg+q], bd1 = g_bd[HDIM+cg+q],
                              bd2 = g_bd[2*HDIM+cg+q], bd3 = g_bd[3*HDIM+cg+q];
                        float bs0 = P0.x*bd0 + P0.y*bd1 + P0.z*bd2 + P0.w*bd3;
                        float bs1 = P1.x*bd0 + P1.y*bd1 + P1.z*bd2 + P1.w*bd3;
                        o0[c+q] += acc[i][j][q]   + bs0;
                        o1[c+q] += acc[i][j][2+q] + bs1;
                    }
                }
            }
        }
    }
}

// ---------------- host ----------------
extern "C" void kernel_launch(void* const* d_in, const int* in_sizes, int n_in,
                              void* d_out, int out_size) {
    const float* x  = (const float*)d_in[0];
    const float* ns = (const float*)d_in[1];
    const float* gw = (const float*)d_in[2];
    const float* wu = (const float*)d_in[3];
    const float* bu = (const float*)d_in[4];
    const float* wd = (const float*)d_in[5];
    const float* bd = (const float*)d_in[6];
    float* out = (float*)d_out;

    int sms = 148;
    cudaDeviceGetAttribute(&sms, cudaDevAttrMultiProcessorCount, 0);

    cudaFuncSetAttribute(gemm_tc<24, 0>,  cudaFuncAttributeMaxDynamicSharedMemorySize, SMEMSZ);
    cudaFuncSetAttribute(gemm_tc<192, 1>, cudaFuncAttributeMaxDynamicSharedMemorySize, SMEMSZ);

    moe_prep<<<T_TOK, 128>>>(x, ns, gw, out);
    moe_convert<<<1024, 256>>>(wu, wd, bu, bd);
    gemm_tc<24, 0><<<sms, 288, SMEMSZ>>>(96 * 64, nullptr);   // all 4 up-GEMMs
    gemm_tc<192, 1><<<sms, 288, SMEMSZ>>>(6 * 64, out);       // fused down-GEMM, K=12288
}

// round 10
// speedup vs baseline: 3.7842x; 3.7842x over previous
#include <cuda_runtime.h>
#include <cuda_fp16.h>
#include <cstdint>
#include <cstddef>

#define T_TOK 8192
#define HDIM  1536
#define I2    6144
#define IH    3072
#define ALPHA 1.702f
#define LIMIT 7.0f
#define NSTG  4
#define STGB  49152
#define SMEMSZ (NSTG * STGB + 1024)   // +1KB so the stage base can be 1024-aligned

// tiled + SW128-swizzled fp16 operand storage (K-major, 64-half K-blocks)
__device__ __align__(1024) __half g_xn [(size_t)T_TOK * HDIM];
__device__ __align__(1024) __half g_act[(size_t)T_TOK * IH * 4];
__device__ __align__(1024) __half g_wu [(size_t)4 * I2 * HDIM];
__device__ __align__(1024) __half g_wd [(size_t)4 * HDIM * IH];
__device__ float g_probs[T_TOK * 4];
__device__ float g_bu[4 * I2];
__device__ float g_bd[4 * HDIM];
__device__ int   g_eids[4];

__device__ __forceinline__ uint32_t smem_u32(const void* p) {
    uint32_t a;
    asm("{ .reg .u64 t; cvta.to.shared.u64 t, %1; cvt.u32.u64 %0, t; }" : "=r"(a) : "l"(p));
    return a;
}
__device__ __forceinline__ uint32_t h2u(__half2 h) {
    union { __half2 h; uint32_t u; } c; c.h = h; return c.u;
}

#define MBAR_INIT(a, c) \
    asm volatile("mbarrier.init.shared.b64 [%0], %1;" :: "r"((uint32_t)(a)), "r"((uint32_t)(c)) : "memory")
#define MBAR_EXPECT(a, b) \
    asm volatile("mbarrier.arrive.expect_tx.shared.b64 _, [%0], %1;" :: "r"((uint32_t)(a)), "r"((uint32_t)(b)) : "memory")
#define MBAR_ARRIVE(a) \
    asm volatile("mbarrier.arrive.shared.b64 _, [%0];" :: "r"((uint32_t)(a)) : "memory")
#define MBAR_WAIT(a, p) do { \
    uint32_t _m = (uint32_t)(a), _p = (uint32_t)(p), _d; \
    asm volatile("{\n\t.reg .pred q;\n\t" \
        "mbarrier.try_wait.parity.acquire.cta.shared::cta.b64 q, [%1], %2;\n\t" \
        "selp.b32 %0, 1, 0, q;\n\t}" : "=r"(_d) : "r"(_m), "r"(_p) : "memory"); \
    if (!_d) { \
        asm volatile("{\n\t.reg .pred Q;\n\tL%=:\n\t" \
            "mbarrier.try_wait.parity.acquire.cta.shared::cta.b64 Q, [%0], %1, 0x989680;\n\t" \
            "@Q bra.uni D%=;\n\tbra.uni L%=;\n\tD%=:\n\t}" \
            :: "r"(_m), "r"(_p) : "memory"); \
    } \
} while (0)
#define BULK(sdst, gsrc, sz, mbar) \
    asm volatile("cp.async.bulk.shared::cluster.global.mbarrier::complete_tx::bytes " \
                 "[%0], [%1], %2, [%3];" \
                 :: "r"((uint32_t)(sdst)), "l"(gsrc), "r"((uint32_t)(sz)), "r"((uint32_t)(mbar)) : "memory")
#define LDSM4(a0,a1,a2,a3,addr) \
    asm volatile("ldmatrix.sync.aligned.m8n8.x4.shared.b16 {%0,%1,%2,%3}, [%4];" \
        : "=r"(a0),"=r"(a1),"=r"(a2),"=r"(a3) : "r"(addr))
#define MMA(c,a,b) \
    asm volatile("mma.sync.aligned.m16n8k16.row.col.f32.f16.f16.f32 " \
        "{%0,%1,%2,%3},{%4,%5,%6,%7},{%8,%9},{%0,%1,%2,%3};" \
        : "+f"((c)[0]),"+f"((c)[1]),"+f"((c)[2]),"+f"((c)[3]) \
        : "r"((a)[0]),"r"((a)[1]),"r"((a)[2]),"r"((a)[3]),"r"((b)[0]),"r"((b)[1]))

// ------- prep: RMSNorm -> g_xn (tiled fp16) + out=x + router (fused) --------
__global__ void moe_prep(const float* __restrict__ x, const float* __restrict__ ns,
                         const float* __restrict__ gw, float* __restrict__ out) {
    int t = blockIdx.x, tid = threadIdx.x, lane = tid & 31, w = tid >> 5;  // 128 thr
    __shared__ float4 sxn[HDIM / 4];
    __shared__ float sred[4], slog[16];
    const float4* xr = (const float4*)(x + (size_t)t * HDIM);
    float4 v[3]; float ss = 0.f;
#pragma unroll
    for (int i = 0; i < 3; ++i) {
        v[i] = xr[tid + i * 128];
        ss += v[i].x*v[i].x + v[i].y*v[i].y + v[i].z*v[i].z + v[i].w*v[i].w;
    }
#pragma unroll
    for (int o = 16; o; o >>= 1) ss += __shfl_xor_sync(0xFFFFFFFFu, ss, o);
    if (lane == 0) sred[w] = ss;
    __syncthreads();
    float rs = rsqrtf((sred[0]+sred[1]+sred[2]+sred[3]) / (float)HDIM + 1e-6f);
    float4* outr = (float4*)(out + (size_t)t * HDIM);
    const float4* sc = (const float4*)ns;
    int mb = t >> 7, r = t & 127;
#pragma unroll
    for (int i = 0; i < 3; ++i) {
        int idx = tid + i * 128;
        float4 s4 = sc[idx], xv = v[i];
        outr[idx] = xv;
        float4 xn = make_float4(xv.x*rs*s4.x, xv.y*rs*s4.y, xv.z*rs*s4.z, xv.w*rs*s4.w);
        sxn[idx] = xn;
        int k0 = idx * 4, kb = k0 >> 6, c8 = (k0 & 63) >> 3;
        __half* dst = g_xn + ((size_t)(mb*24 + kb))*8192 + r*64 + ((c8 ^ (r & 7)) * 8) + (k0 & 7);
        *(uint2*)dst = make_uint2(h2u(__floats2half2_rn(xn.x, xn.y)),
                                  h2u(__floats2half2_rn(xn.z, xn.w)));
    }
    __syncthreads();
#pragma unroll
    for (int e = 0; e < 4; ++e) {
        const float4* ge = (const float4*)(gw + (size_t)(4*w + e) * HDIM);
        float d = 0.f;
#pragma unroll
        for (int i = 0; i < 12; ++i) {
            int idx = lane + i * 32;
            float4 a = sxn[idx], b = ge[idx];
            d += a.x*b.x + a.y*b.y + a.z*b.z + a.w*b.w;
        }
#pragma unroll
        for (int o = 16; o; o >>= 1) d += __shfl_xor_sync(0xFFFFFFFFu, d, o);
        if (lane == 0) slog[4*w + e] = d;
    }
    __syncthreads();
    if (tid == 0) {
        float vv[16]; unsigned used = 0; float tv[4]; int ti[4];
#pragma unroll
        for (int e = 0; e < 16; ++e) vv[e] = slog[e];
#pragma unroll
        for (int i = 0; i < 4; ++i) {
            float best = -1e30f; int bi = 0;
#pragma unroll
            for (int e = 0; e < 16; ++e)
                if (!((used>>e)&1u) && vv[e] > best) { best = vv[e]; bi = e; }
            used |= 1u << bi; tv[i] = best; ti[i] = bi;
        }
        float mx = tv[0], sum = 0.f, pr[4];
#pragma unroll
        for (int i = 0; i < 4; ++i) { pr[i] = expf(tv[i]-mx); sum += pr[i]; }
#pragma unroll
        for (int i = 0; i < 4; ++i) g_probs[t*4+i] = pr[i] / sum;
        if (t == 0) { for (int i = 0; i < 4; ++i) g_eids[i] = ti[i]; }
    }
}

// -------- convert: gather 4 experts, fp32->fp16, retile + swizzle ------------
__global__ void moe_convert(const float* __restrict__ wu, const float* __restrict__ wd,
                            const float* __restrict__ bu, const float* __restrict__ bd) {
    const int NU = I2*HDIM/8, ND = HDIM*IH/8, PER = NU + ND;
    const long long total = 4ll * PER;
    long long stride = (long long)gridDim.x * blockDim.x;
    for (long long i = (long long)blockIdx.x*blockDim.x + threadIdx.x; i < total; i += stride) {
        int slot = (int)(i / PER), r = (int)(i - (long long)slot * PER);
        int eid = g_eids[slot];
        const float4* src; __half* dst;
        if (r < NU) {
            int row = r / 192, k0 = (r % 192) * 8;
            src = (const float4*)(wu + (size_t)eid*I2*HDIM + (size_t)row*HDIM + k0);
            int lin = row >= IH, a = lin ? row - IH : row;
            int nb = slot*24 + (a >> 7), ar = a & 127;
            int rr = (ar >> 3) * 16 + (lin ? 8 : 0) + (ar & 7);
            int kb = k0 >> 6, c8 = (k0 & 63) >> 3;
            dst = g_wu + ((size_t)(nb*24 + kb))*16384 + rr*64 + ((c8 ^ (rr & 7)) * 8);
        } else {
            int r2 = r - NU;
            int row = r2 / 384, k0 = (r2 % 384) * 8;
            src = (const float4*)(wd + (size_t)eid*HDIM*IH + (size_t)row*IH + k0);
            int nb = row >> 8, rr = row & 255;
            int kbg = slot*48 + (k0 >> 6), c8 = (k0 & 63) >> 3;
            dst = g_wd + ((size_t)(nb*192 + kbg))*16384 + rr*64 + ((c8 ^ (rr & 7)) * 8);
        }
        float4 a = src[0], b = src[1];
        *(uint4*)dst = make_uint4(h2u(__floats2half2_rn(a.x,a.y)), h2u(__floats2half2_rn(a.z,a.w)),
                                  h2u(__floats2half2_rn(b.x,b.y)), h2u(__floats2half2_rn(b.z,b.w)));
    }
    int gt = blockIdx.x*blockDim.x + threadIdx.x;
    if (gt < 4*(I2+HDIM)) {
        int slot = gt/(I2+HDIM), j = gt%(I2+HDIM), eid = g_eids[slot];
        if (j < I2) g_bu[slot*I2+j] = bu[(size_t)eid*I2 + j];
        else        g_bd[slot*HDIM + (j-I2)] = bd[(size_t)eid*HDIM + (j-I2)];
    }
}

// ------- persistent GEMM: 128x256 x K(64/stage), single-buffer frags --------
template <int KSTEPS, int EPI>
__global__ __launch_bounds__(288, 1) void gemm_tc(int ntiles, float* __restrict__ dout) {
    extern __shared__ char smem[];
    __shared__ __align__(8) unsigned long long mbar[2 * NSTG];
    uint32_t sb = (smem_u32(smem) + 1023u) & ~1023u;   // 1024-aligned stage base
    uint32_t mb0 = smem_u32(&mbar[0]);
    const int tid = threadIdx.x, lane = tid & 31, wid = tid >> 5;

    if (tid == 0) {
#pragma unroll
        for (int s = 0; s < NSTG; ++s) { MBAR_INIT(mb0 + 8*s, 1); MBAR_INIT(mb0 + 8*(NSTG+s), 8); }
        asm volatile("fence.proxy.async.shared::cta;" ::: "memory");
    }
    __syncthreads();

    if (wid == 8) {  // producer warp
        if (lane == 0) {
            int st = 0; uint32_t ph = 1;
            for (int tile = blockIdx.x; tile < ntiles; tile += gridDim.x) {
                int nb = tile >> 6, mb = tile & 63;
                const char* Ab = (const char*)(EPI ? g_act : g_xn) + (size_t)mb * KSTEPS * 16384;
                const char* Bb = (const char*)(EPI ? g_wd : g_wu) + (size_t)nb * KSTEPS * 32768;
                for (int s = 0; s < KSTEPS; ++s) {
                    MBAR_WAIT(mb0 + 8*(NSTG+st), ph);
                    MBAR_EXPECT(mb0 + 8*st, STGB);
                    uint32_t sa = sb + st * STGB;
                    BULK(sa,         Ab + (size_t)s * 16384, 16384, mb0 + 8*st);
                    BULK(sa + 16384, Bb + (size_t)s * 32768, 32768, mb0 + 8*st);
                    if (++st == NSTG) { st = 0; ph ^= 1; }
                }
            }
        }
        return;
    }

    const int wm = (wid >> 2) * 64, wn = (wid & 3) * 64;
    const int lh = lane >> 4, grp = lane >> 3;
    uint32_t baseA[4], baseB[4];
#pragma unroll
    for (int i = 0; i < 4; ++i) {
        int ro = wm + i*16 + (lane & 15);
        baseA[i] = ro*128 + ((((ro & 7) ^ lh)) << 4);
    }
#pragma unroll
    for (int j = 0; j < 4; ++j) {
        int ro = wn + (2*j + (grp >> 1))*8 + (lane & 7);
        baseB[j] = 16384 + ro*128 + ((((ro & 7) ^ (grp & 1))) << 4);
    }

    int st = 0; uint32_t phF = 0;
    for (int tile = blockIdx.x; tile < ntiles; tile += gridDim.x) {
        int nb = tile >> 6, mb = tile & 63;
        float acc[4][8][4];
#pragma unroll
        for (int i = 0; i < 4; ++i)
#pragma unroll
            for (int j = 0; j < 8; ++j)
#pragma unroll
                for (int q = 0; q < 4; ++q) acc[i][j][q] = 0.f;

        for (int s = 0; s < KSTEPS; ++s) {
            MBAR_WAIT(mb0 + 8*st, phF);
            uint32_t sA = sb + st * STGB;
#pragma unroll
            for (int ks = 0; ks < 4; ++ks) {
                uint32_t a[4][4], b[8][2];
#pragma unroll
                for (int i = 0; i < 4; ++i)
                    LDSM4(a[i][0],a[i][1],a[i][2],a[i][3], sA + (baseA[i] ^ (ks << 5)));
#pragma unroll
                for (int j = 0; j < 4; ++j)
                    LDSM4(b[2*j][0],b[2*j][1],b[2*j+1][0],b[2*j+1][1],
                          sA + (baseB[j] ^ (ks << 5)));
                if (ks == 3 && lane == 0) MBAR_ARRIVE(mb0 + 8*(NSTG + st));
#pragma unroll
                for (int i = 0; i < 4; ++i)
#pragma unroll
                    for (int j = 0; j < 8; ++j) MMA(acc[i][j], a[i], b[j]);
            }
            if (++st == NSTG) { st = 0; phF ^= 1; }
        }

        if (EPI == 0) {
            int slot = nb / 24, nbl = nb - slot * 24;
            const float* bug = g_bu + slot*I2 + nbl*128;
            const float* bul = bug + IH;
#pragma unroll
            for (int i = 0; i < 4; ++i) {
                int r = wm + i*16 + (lane >> 2);
                float p0 = g_probs[(mb*128 + r)*4 + slot];
                float p1 = g_probs[(mb*128 + r + 8)*4 + slot];
#pragma unroll
                for (int t = 0; t < 4; ++t) {
                    int ac = (wn >> 1) + t*8 + (lane & 3) * 2;
                    float bg0 = bug[ac], bg1 = bug[ac+1], bl0 = bul[ac], bl1 = bul[ac+1];
#pragma unroll
                    for (int h = 0; h < 2; ++h) {
                        int tr = r + h*8;
                        float pp = h ? p1 : p0;
                        float gg0 = acc[i][2*t][2*h]   + bg0, gg1 = acc[i][2*t][2*h+1]   + bg1;
                        float ll0 = acc[i][2*t+1][2*h] + bl0, ll1 = acc[i][2*t+1][2*h+1] + bl1;
                        gg0 = fminf(gg0, LIMIT); gg1 = fminf(gg1, LIMIT);
                        ll0 = fminf(fmaxf(ll0, -LIMIT), LIMIT);
                        ll1 = fminf(fmaxf(ll1, -LIMIT), LIMIT);
                        float a0 = pp * (gg0 / (1.f + __expf(-ALPHA*gg0)) * (ll0 + 1.f));
                        float a1 = pp * (gg1 / (1.f + __expf(-ALPHA*gg1)) * (ll1 + 1.f));
                        int ag = nb*128 + ac;
                        __half* dst = g_act + ((size_t)(mb*192 + (ag >> 6)))*8192
                            + tr*64 + ((((ag & 63) >> 3) ^ (tr & 7)) * 8) + (ac & 7);
                        *(__half2*)dst = __floats2half2_rn(a0, a1);
                    }
                }
            }
        } else {
#pragma unroll
            for (int i = 0; i < 4; ++i) {
                int r = wm + i*16 + (lane >> 2);
                int t0 = mb*128 + r;
                float4 P0 = *(const float4*)&g_probs[t0*4];
                float4 P1 = *(const float4*)&g_probs[(t0+8)*4];
                float* o0 = dout + (size_t)t0*HDIM + nb*256;
                float* o1 = o0 + 8ull*HDIM;
#pragma unroll
                for (int j = 0; j < 8; ++j) {
                    int c = wn + j*8 + (lane & 3) * 2;
                    int cg = nb*256 + c;
#pragma unroll
                    for (int q = 0; q < 2; ++q) {
                        float bd0 = g_bd[cg+q], bd1 = g_bd[HDIM+cg+q],
                              bd2 = g_bd[2*HDIM+cg+q], bd3 = g_bd[3*HDIM+cg+q];
                        float bs0 = P0.x*bd0 + P0.y*bd1 + P0.z*bd2 + P0.w*bd3;
                        float bs1 = P1.x*bd0 + P1.y*bd1 + P1.z*bd2 + P1.w*bd3;
                        o0[c+q] += acc[i][j][q]   + bs0;
                        o1[c+q] += acc[i][j][2+q] + bs1;
                    }
                }
            }
        }
    }
}

// ---------------- host ----------------
extern "C" void kernel_launch(void* const* d_in, const int* in_sizes, int n_in,
                              void* d_out, int out_size) {
    const float* x  = (const float*)d_in[0];
    const float* ns = (const float*)d_in[1];
    const float* gw = (const float*)d_in[2];
    const float* wu = (const float*)d_in[3];
    const float* bu = (const float*)d_in[4];
    const float* wd = (const float*)d_in[5];
    const float* bd = (const float*)d_in[6];
    float* out = (float*)d_out;

    int sms = 148;
    cudaDeviceGetAttribute(&sms, cudaDevAttrMultiProcessorCount, 0);

    cudaFuncSetAttribute(gemm_tc<24, 0>,  cudaFuncAttributeMaxDynamicSharedMemorySize, SMEMSZ);
    cudaFuncSetAttribute(gemm_tc<192, 1>, cudaFuncAttributeMaxDynamicSharedMemorySize, SMEMSZ);

    moe_prep<<<T_TOK, 128>>>(x, ns, gw, out);
    moe_convert<<<1024, 256>>>(wu, wd, bu, bd);
    gemm_tc<24, 0><<<sms, 288, SMEMSZ>>>(96 * 64, nullptr);   // all 4 up-GEMMs
    gemm_tc<192, 1><<<sms, 288, SMEMSZ>>>(6 * 64, out);       // fused down-GEMM, K=12288
}

// round 11
// speedup vs baseline: 4.5219x; 1.1949x over previous
#include <cuda_runtime.h>
#include <cuda_fp16.h>
#include <cstdint>
#include <cstddef>

#define T_TOK 8192
#define HDIM  1536
#define I2    6144
#define IH    3072
#define ALPHA 1.702f
#define LIMIT 7.0f
#define NSTG  4
#define STGB  49152
#define SMEMSZ (NSTG * STGB)

// tiled + SW128-swizzled fp16 operand storage (K-major, 64-half K-blocks)
__device__ __align__(1024) __half g_xn [(size_t)T_TOK * HDIM];
__device__ __align__(1024) __half g_act[(size_t)T_TOK * IH * 4];
__device__ __align__(1024) __half g_wu [(size_t)4 * I2 * HDIM];
__device__ __align__(1024) __half g_wd [(size_t)4 * HDIM * IH];
__device__ float g_probs[T_TOK * 4];
__device__ float g_bu[4 * I2];
__device__ float g_bd[4 * HDIM];
__device__ int   g_eids[4];

__device__ __forceinline__ uint32_t smem_u32(const void* p) {
    uint32_t a;
    asm("{ .reg .u64 t; cvta.to.shared.u64 t, %1; cvt.u32.u64 %0, t; }" : "=r"(a) : "l"(p));
    return a;
}
__device__ __forceinline__ uint32_t h2u(__half2 h) {
    union { __half2 h; uint32_t u; } c; c.h = h; return c.u;
}

#define MBAR_INIT(a, c) \
    asm volatile("mbarrier.init.shared.b64 [%0], %1;" :: "r"((uint32_t)(a)), "r"((uint32_t)(c)) : "memory")
#define MBAR_EXPECT(a, b) \
    asm volatile("mbarrier.arrive.expect_tx.shared.b64 _, [%0], %1;" :: "r"((uint32_t)(a)), "r"((uint32_t)(b)) : "memory")
#define MBAR_ARRIVE(a) \
    asm volatile("mbarrier.arrive.shared.b64 _, [%0];" :: "r"((uint32_t)(a)) : "memory")
#define MBAR_WAIT(a, p) do { \
    uint32_t _m = (uint32_t)(a), _p = (uint32_t)(p), _d; \
    asm volatile("{\n\t.reg .pred q;\n\t" \
        "mbarrier.try_wait.parity.acquire.cta.shared::cta.b64 q, [%1], %2;\n\t" \
        "selp.b32 %0, 1, 0, q;\n\t}" : "=r"(_d) : "r"(_m), "r"(_p) : "memory"); \
    if (!_d) { \
        asm volatile("{\n\t.reg .pred Q;\n\tL%=:\n\t" \
            "mbarrier.try_wait.parity.acquire.cta.shared::cta.b64 Q, [%0], %1, 0x989680;\n\t" \
            "@Q bra.uni D%=;\n\tbra.uni L%=;\n\tD%=:\n\t}" \
            :: "r"(_m), "r"(_p) : "memory"); \
    } \
} while (0)
#define BULK(sdst, gsrc, sz, mbar) \
    asm volatile("cp.async.bulk.shared::cluster.global.mbarrier::complete_tx::bytes " \
                 "[%0], [%1], %2, [%3];" \
                 :: "r"((uint32_t)(sdst)), "l"(gsrc), "r"((uint32_t)(sz)), "r"((uint32_t)(mbar)) : "memory")
#define LDSM4(a0,a1,a2,a3,addr) \
    asm volatile("ldmatrix.sync.aligned.m8n8.x4.shared.b16 {%0,%1,%2,%3}, [%4];" \
        : "=r"(a0),"=r"(a1),"=r"(a2),"=r"(a3) : "r"(addr))
#define MMA(c,a,b) \
    asm volatile("mma.sync.aligned.m16n8k16.row.col.f32.f16.f16.f32 " \
        "{%0,%1,%2,%3},{%4,%5,%6,%7},{%8,%9},{%0,%1,%2,%3};" \
        : "+f"((c)[0]),"+f"((c)[1]),"+f"((c)[2]),"+f"((c)[3]) \
        : "r"((a)[0]),"r"((a)[1]),"r"((a)[2]),"r"((a)[3]),"r"((b)[0]),"r"((b)[1]))
#define REDADD(ptr, val) \
    asm volatile("red.global.add.f32 [%0], %1;" :: "l"(ptr), "f"(val) : "memory")

// ------- prep: RMSNorm -> g_xn (tiled fp16) + out=x + router (fused) --------
__global__ void moe_prep(const float* __restrict__ x, const float* __restrict__ ns,
                         const float* __restrict__ gw, float* __restrict__ out) {
    int t = blockIdx.x, tid = threadIdx.x, lane = tid & 31, w = tid >> 5;  // 128 thr
    __shared__ float4 sxn[HDIM / 4];
    __shared__ float sred[4], slog[16];
    const float4* xr = (const float4*)(x + (size_t)t * HDIM);
    float4 v[3]; float ss = 0.f;
#pragma unroll
    for (int i = 0; i < 3; ++i) {
        v[i] = xr[tid + i * 128];
        ss += v[i].x*v[i].x + v[i].y*v[i].y + v[i].z*v[i].z + v[i].w*v[i].w;
    }
#pragma unroll
    for (int o = 16; o; o >>= 1) ss += __shfl_xor_sync(0xFFFFFFFFu, ss, o);
    if (lane == 0) sred[w] = ss;
    __syncthreads();
    float rs = rsqrtf((sred[0]+sred[1]+sred[2]+sred[3]) / (float)HDIM + 1e-6f);
    float4* outr = (float4*)(out + (size_t)t * HDIM);
    const float4* sc = (const float4*)ns;
    int mb = t >> 7, r = t & 127;
#pragma unroll
    for (int i = 0; i < 3; ++i) {
        int idx = tid + i * 128;
        float4 s4 = sc[idx], xv = v[i];
        outr[idx] = xv;
        float4 xn = make_float4(xv.x*rs*s4.x, xv.y*rs*s4.y, xv.z*rs*s4.z, xv.w*rs*s4.w);
        sxn[idx] = xn;
        int k0 = idx * 4, kb = k0 >> 6, c8 = (k0 & 63) >> 3;
        __half* dst = g_xn + ((size_t)(mb*24 + kb))*8192 + r*64 + ((c8 ^ (r & 7)) * 8) + (k0 & 7);
        *(uint2*)dst = make_uint2(h2u(__floats2half2_rn(xn.x, xn.y)),
                                  h2u(__floats2half2_rn(xn.z, xn.w)));
    }
    __syncthreads();
#pragma unroll
    for (int e = 0; e < 4; ++e) {
        const float4* ge = (const float4*)(gw + (size_t)(4*w + e) * HDIM);
        float d = 0.f;
#pragma unroll
        for (int i = 0; i < 12; ++i) {
            int idx = lane + i * 32;
            float4 a = sxn[idx], b = ge[idx];
            d += a.x*b.x + a.y*b.y + a.z*b.z + a.w*b.w;
        }
#pragma unroll
        for (int o = 16; o; o >>= 1) d += __shfl_xor_sync(0xFFFFFFFFu, d, o);
        if (lane == 0) slog[4*w + e] = d;
    }
    __syncthreads();
    if (tid == 0) {
        float vv[16]; unsigned used = 0; float tv[4]; int ti[4];
#pragma unroll
        for (int e = 0; e < 16; ++e) vv[e] = slog[e];
#pragma unroll
        for (int i = 0; i < 4; ++i) {
            float best = -1e30f; int bi = 0;
#pragma unroll
            for (int e = 0; e < 16; ++e)
                if (!((used>>e)&1u) && vv[e] > best) { best = vv[e]; bi = e; }
            used |= 1u << bi; tv[i] = best; ti[i] = bi;
        }
        float mx = tv[0], sum = 0.f, pr[4];
#pragma unroll
        for (int i = 0; i < 4; ++i) { pr[i] = expf(tv[i]-mx); sum += pr[i]; }
#pragma unroll
        for (int i = 0; i < 4; ++i) g_probs[t*4+i] = pr[i] / sum;
        if (t == 0) { for (int i = 0; i < 4; ++i) g_eids[i] = ti[i]; }
    }
}

// -------- convert: gather 4 experts, fp32->fp16, retile + swizzle ------------
__global__ void moe_convert(const float* __restrict__ wu, const float* __restrict__ wd,
                            const float* __restrict__ bu, const float* __restrict__ bd) {
    const int NU = I2*HDIM/8, ND = HDIM*IH/8, PER = NU + ND;
    const long long total = 4ll * PER;
    long long stride = (long long)gridDim.x * blockDim.x;
    for (long long i = (long long)blockIdx.x*blockDim.x + threadIdx.x; i < total; i += stride) {
        int slot = (int)(i / PER), r = (int)(i - (long long)slot * PER);
        int eid = g_eids[slot];
        const float4* src; __half* dst;
        if (r < NU) {
            int row = r / 192, k0 = (r % 192) * 8;
            src = (const float4*)(wu + (size_t)eid*I2*HDIM + (size_t)row*HDIM + k0);
            int lin = row >= IH, a = lin ? row - IH : row;
            int nb = slot*24 + (a >> 7), ar = a & 127;
            int rr = (ar >> 3) * 16 + (lin ? 8 : 0) + (ar & 7);
            int kb = k0 >> 6, c8 = (k0 & 63) >> 3;
            dst = g_wu + ((size_t)(nb*24 + kb))*16384 + rr*64 + ((c8 ^ (rr & 7)) * 8);
        } else {
            int r2 = r - NU;
            int row = r2 / 384, k0 = (r2 % 384) * 8;
            src = (const float4*)(wd + (size_t)eid*HDIM*IH + (size_t)row*IH + k0);
            int nb = row >> 8, rr = row & 255;
            int kbg = slot*48 + (k0 >> 6), c8 = (k0 & 63) >> 3;
            dst = g_wd + ((size_t)(nb*192 + kbg))*16384 + rr*64 + ((c8 ^ (rr & 7)) * 8);
        }
        float4 a = src[0], b = src[1];
        *(uint4*)dst = make_uint4(h2u(__floats2half2_rn(a.x,a.y)), h2u(__floats2half2_rn(a.z,a.w)),
                                  h2u(__floats2half2_rn(b.x,b.y)), h2u(__floats2half2_rn(b.z,b.w)));
    }
    int gt = blockIdx.x*blockDim.x + threadIdx.x;
    if (gt < 4*(I2+HDIM)) {
        int slot = gt/(I2+HDIM), j = gt%(I2+HDIM), eid = g_eids[slot];
        if (j < I2) g_bu[slot*I2+j] = bu[(size_t)eid*I2 + j];
        else        g_bd[slot*HDIM + (j-I2)] = bd[(size_t)eid*HDIM + (j-I2)];
    }
}

// ------- persistent GEMM: 128x256 x K(64/stage), bulk-async, 8 HMMA warps ---
// EPI 0 (up):  unit=(nb<96, mb<64), KSTEPS=24; SwiGLU*prob -> g_act
// EPI 1 (down):unit=(kc<3, nb<6, mb<64), KSTEPS=64; red.global.add into out
template <int KSTEPS, int EPI>
__global__ __launch_bounds__(288, 1) void gemm_tc(int ntiles, float* __restrict__ dout) {
    extern __shared__ char smem[];
    __shared__ __align__(8) unsigned long long mbar[2 * NSTG];
    uint32_t sb = smem_u32(smem);
    uint32_t mb0 = smem_u32(&mbar[0]);
    const int tid = threadIdx.x, lane = tid & 31, wid = tid >> 5;

    if (tid == 0) {
#pragma unroll
        for (int s = 0; s < NSTG; ++s) { MBAR_INIT(mb0 + 8*s, 1); MBAR_INIT(mb0 + 8*(NSTG+s), 8); }
        asm volatile("fence.proxy.async.shared::cta;" ::: "memory");
    }
    __syncthreads();

    if (wid == 8) {  // producer warp
        if (lane == 0) {
            int st = 0; uint32_t ph = 1;
            for (int tile = blockIdx.x; tile < ntiles; tile += gridDim.x) {
                int mb = tile & 63, rest = tile >> 6;
                int nb = EPI ? (rest % 6) : rest;
                int kc = EPI ? (rest / 6) : 0;
                const char* Ab = EPI
                    ? (const char*)g_act + ((size_t)mb*192 + kc*64) * 16384
                    : (const char*)g_xn  + ((size_t)mb*24) * 16384;
                const char* Bb = EPI
                    ? (const char*)g_wd + ((size_t)nb*192 + kc*64) * 32768
                    : (const char*)g_wu + ((size_t)nb*24) * 32768;
                for (int s = 0; s < KSTEPS; ++s) {
                    MBAR_WAIT(mb0 + 8*(NSTG+st), ph);
                    MBAR_EXPECT(mb0 + 8*st, STGB);
                    uint32_t sa = sb + st * STGB;
                    BULK(sa,         Ab + (size_t)s * 16384, 16384, mb0 + 8*st);
                    BULK(sa + 16384, Bb + (size_t)s * 32768, 32768, mb0 + 8*st);
                    if (++st == NSTG) { st = 0; ph ^= 1; }
                }
            }
        }
        return;
    }

    const int wm = (wid >> 2) * 64, wn = (wid & 3) * 64;
    int st = 0; uint32_t phF = 0;
    for (int tile = blockIdx.x; tile < ntiles; tile += gridDim.x) {
        int mb = tile & 63, rest = tile >> 6;
        int nb = EPI ? (rest % 6) : rest;
        int kc = EPI ? (rest / 6) : 0;
        float acc[4][8][4];
#pragma unroll
        for (int i = 0; i < 4; ++i)
#pragma unroll
            for (int j = 0; j < 8; ++j)
#pragma unroll
                for (int q = 0; q < 4; ++q) acc[i][j][q] = 0.f;

        for (int s = 0; s < KSTEPS; ++s) {
            MBAR_WAIT(mb0 + 8*st, phF);
            uint32_t sA = sb + st * STGB, sB = sA + 16384;
#pragma unroll
            for (int ks = 0; ks < 4; ++ks) {
                uint32_t a[4][4], b[8][2];
#pragma unroll
                for (int i = 0; i < 4; ++i) {
                    int ro = wm + i*16 + (lane & 15), ko = ks*16 + ((lane >> 4) << 3);
                    LDSM4(a[i][0],a[i][1],a[i][2],a[i][3],
                          sA + ro*128 + ((((ko >> 3) ^ (ro & 7))) << 4));
                }
#pragma unroll
                for (int j = 0; j < 8; j += 2) {
                    int grp = lane >> 3;
                    int ro = wn + (j + (grp >> 1))*8 + (lane & 7);
                    int ko = ks*16 + ((grp & 1) << 3);
                    LDSM4(b[j][0],b[j][1],b[j+1][0],b[j+1][1],
                          sB + ro*128 + ((((ko >> 3) ^ (ro & 7))) << 4));
                }
#pragma unroll
                for (int i = 0; i < 4; ++i)
#pragma unroll
                    for (int j = 0; j < 8; ++j) MMA(acc[i][j], a[i], b[j]);
            }
            if (lane == 0) MBAR_ARRIVE(mb0 + 8*(NSTG + st));
            if (++st == NSTG) { st = 0; phF ^= 1; }
        }

        if (EPI == 0) {
            int slot = nb / 24, nbl = nb - slot * 24;
            const float* bug = g_bu + slot*I2 + nbl*128;
            const float* bul = bug + IH;
#pragma unroll
            for (int i = 0; i < 4; ++i) {
                int r = wm + i*16 + (lane >> 2);
                float p0 = g_probs[(mb*128 + r)*4 + slot];
                float p1 = g_probs[(mb*128 + r + 8)*4 + slot];
#pragma unroll
                for (int t = 0; t < 4; ++t) {
                    int ac = (wn >> 1) + t*8 + (lane & 3) * 2;
                    float bg0 = bug[ac], bg1 = bug[ac+1], bl0 = bul[ac], bl1 = bul[ac+1];
#pragma unroll
                    for (int h = 0; h < 2; ++h) {
                        int tr = r + h*8;
                        float pp = h ? p1 : p0;
                        float gg0 = acc[i][2*t][2*h]   + bg0, gg1 = acc[i][2*t][2*h+1]   + bg1;
                        float ll0 = acc[i][2*t+1][2*h] + bl0, ll1 = acc[i][2*t+1][2*h+1] + bl1;
                        gg0 = fminf(gg0, LIMIT); gg1 = fminf(gg1, LIMIT);
                        ll0 = fminf(fmaxf(ll0, -LIMIT), LIMIT);
                        ll1 = fminf(fmaxf(ll1, -LIMIT), LIMIT);
                        float a0 = pp * (gg0 / (1.f + __expf(-ALPHA*gg0)) * (ll0 + 1.f));
                        float a1 = pp * (gg1 / (1.f + __expf(-ALPHA*gg1)) * (ll1 + 1.f));
                        int ag = nb*128 + ac;
                        __half* dst = g_act + ((size_t)(mb*192 + (ag >> 6)))*8192
                            + tr*64 + ((((ag & 63) >> 3) ^ (tr & 7)) * 8) + (ac & 7);
                        *(__half2*)dst = __floats2half2_rn(a0, a1);
                    }
                }
            }
        } else {
#pragma unroll
            for (int i = 0; i < 4; ++i) {
                int r = wm + i*16 + (lane >> 2);
                int t0 = mb*128 + r;
                float4 P0 = *(const float4*)&g_probs[t0*4];
                float4 P1 = *(const float4*)&g_probs[(t0+8)*4];
                float* o0 = dout + (size_t)t0*HDIM + nb*256;
                float* o1 = o0 + 8ull*HDIM;
#pragma unroll
                for (int j = 0; j < 8; ++j) {
                    int c = wn + j*8 + (lane & 3) * 2;
                    int cg = nb*256 + c;
#pragma unroll
                    for (int q = 0; q < 2; ++q) {
                        float bs0 = 0.f, bs1 = 0.f;
                        if (kc == 0) {
                            float bd0 = g_bd[cg+q], bd1 = g_bd[HDIM+cg+q],
                                  bd2 = g_bd[2*HDIM+cg+q], bd3 = g_bd[3*HDIM+cg+q];
                            bs0 = P0.x*bd0 + P0.y*bd1 + P0.z*bd2 + P0.w*bd3;
                            bs1 = P1.x*bd0 + P1.y*bd1 + P1.z*bd2 + P1.w*bd3;
                        }
                        REDADD(o0 + c + q, acc[i][j][q]   + bs0);
                        REDADD(o1 + c + q, acc[i][j][2+q] + bs1);
                    }
                }
            }
        }
    }
}

// ---------------- host ----------------
extern "C" void kernel_launch(void* const* d_in, const int* in_sizes, int n_in,
                              void* d_out, int out_size) {
    const float* x  = (const float*)d_in[0];
    const float* ns = (const float*)d_in[1];
    const float* gw = (const float*)d_in[2];
    const float* wu = (const float*)d_in[3];
    const float* bu = (const float*)d_in[4];
    const float* wd = (const float*)d_in[5];
    const float* bd = (const float*)d_in[6];
    float* out = (float*)d_out;

    int sms = 148;
    cudaDeviceGetAttribute(&sms, cudaDevAttrMultiProcessorCount, 0);

    cudaFuncSetAttribute(gemm_tc<24, 0>, cudaFuncAttributeMaxDynamicSharedMemorySize, SMEMSZ);
    cudaFuncSetAttribute(gemm_tc<64, 1>, cudaFuncAttributeMaxDynamicSharedMemorySize, SMEMSZ);

    moe_prep<<<T_TOK, 128>>>(x, ns, gw, out);
    moe_convert<<<1024, 256>>>(wu, wd, bu, bd);
    gemm_tc<24, 0><<<sms, 288, SMEMSZ>>>(96 * 64, nullptr);       // all 4 up-GEMMs
    gemm_tc<64, 1><<<sms, 288, SMEMSZ>>>(3 * 6 * 64, out);        // down, K-split x3
}

// round 12
// speedup vs baseline: 4.5702x; 1.0107x over previous
#include <cuda_runtime.h>
#include <cuda_fp16.h>
#include <cstdint>
#include <cstddef>

#define T_TOK 8192
#define HDIM  1536
#define I2    6144
#define IH    3072
#define ALPHA 1.702f
#define LIMIT 7.0f
#define NSTG  3
#define STGB  32768
#define SMEMSZ (NSTG * STGB)   // 96KB per CTA -> 2 CTAs/SM

// tiled + SW128-swizzled fp16 operand storage (K-major, 64-half K-blocks)
// A tiles: 128 rows x 64 k = 16KB. B tiles: 128 rows x 64 k = 16KB.
__device__ __align__(1024) __half g_xn [(size_t)T_TOK * HDIM];
__device__ __align__(1024) __half g_act[(size_t)T_TOK * IH * 4];
__device__ __align__(1024) __half g_wu [(size_t)4 * I2 * HDIM];
__device__ __align__(1024) __half g_wd [(size_t)4 * HDIM * IH];
__device__ float g_probs[T_TOK * 4];
__device__ float g_bu[4 * I2];
__device__ float g_bd[4 * HDIM];
__device__ int   g_eids[4];

__device__ __forceinline__ uint32_t smem_u32(const void* p) {
    uint32_t a;
    asm("{ .reg .u64 t; cvta.to.shared.u64 t, %1; cvt.u32.u64 %0, t; }" : "=r"(a) : "l"(p));
    return a;
}
__device__ __forceinline__ uint32_t h2u(__half2 h) {
    union { __half2 h; uint32_t u; } c; c.h = h; return c.u;
}

#define MBAR_INIT(a, c) \
    asm volatile("mbarrier.init.shared.b64 [%0], %1;" :: "r"((uint32_t)(a)), "r"((uint32_t)(c)) : "memory")
#define MBAR_EXPECT(a, b) \
    asm volatile("mbarrier.arrive.expect_tx.shared.b64 _, [%0], %1;" :: "r"((uint32_t)(a)), "r"((uint32_t)(b)) : "memory")
#define MBAR_ARRIVE(a) \
    asm volatile("mbarrier.arrive.shared.b64 _, [%0];" :: "r"((uint32_t)(a)) : "memory")
#define MBAR_WAIT(a, p) do { \
    uint32_t _m = (uint32_t)(a), _p = (uint32_t)(p), _d; \
    asm volatile("{\n\t.reg .pred q;\n\t" \
        "mbarrier.try_wait.parity.acquire.cta.shared::cta.b64 q, [%1], %2;\n\t" \
        "selp.b32 %0, 1, 0, q;\n\t}" : "=r"(_d) : "r"(_m), "r"(_p) : "memory"); \
    if (!_d) { \
        asm volatile("{\n\t.reg .pred Q;\n\tL%=:\n\t" \
            "mbarrier.try_wait.parity.acquire.cta.shared::cta.b64 Q, [%0], %1, 0x989680;\n\t" \
            "@Q bra.uni D%=;\n\tbra.uni L%=;\n\tD%=:\n\t}" \
            :: "r"(_m), "r"(_p) : "memory"); \
    } \
} while (0)
#define BULK(sdst, gsrc, sz, mbar) \
    asm volatile("cp.async.bulk.shared::cluster.global.mbarrier::complete_tx::bytes " \
                 "[%0], [%1], %2, [%3];" \
                 :: "r"((uint32_t)(sdst)), "l"(gsrc), "r"((uint32_t)(sz)), "r"((uint32_t)(mbar)) : "memory")
#define LDSM4(a0,a1,a2,a3,addr) \
    asm volatile("ldmatrix.sync.aligned.m8n8.x4.shared.b16 {%0,%1,%2,%3}, [%4];" \
        : "=r"(a0),"=r"(a1),"=r"(a2),"=r"(a3) : "r"(addr))
#define MMA(c,a,b) \
    asm volatile("mma.sync.aligned.m16n8k16.row.col.f32.f16.f16.f32 " \
        "{%0,%1,%2,%3},{%4,%5,%6,%7},{%8,%9},{%0,%1,%2,%3};" \
        : "+f"((c)[0]),"+f"((c)[1]),"+f"((c)[2]),"+f"((c)[3]) \
        : "r"((a)[0]),"r"((a)[1]),"r"((a)[2]),"r"((a)[3]),"r"((b)[0]),"r"((b)[1]))
#define REDADD(ptr, val) \
    asm volatile("red.global.add.f32 [%0], %1;" :: "l"(ptr), "f"(val) : "memory")

// ------- prep: RMSNorm -> g_xn (tiled fp16) + out=x + router (fused) --------
__global__ void moe_prep(const float* __restrict__ x, const float* __restrict__ ns,
                         const float* __restrict__ gw, float* __restrict__ out) {
    int t = blockIdx.x, tid = threadIdx.x, lane = tid & 31, w = tid >> 5;  // 128 thr
    __shared__ float4 sxn[HDIM / 4];
    __shared__ float sred[4], slog[16];
    const float4* xr = (const float4*)(x + (size_t)t * HDIM);
    float4 v[3]; float ss = 0.f;
#pragma unroll
    for (int i = 0; i < 3; ++i) {
        v[i] = xr[tid + i * 128];
        ss += v[i].x*v[i].x + v[i].y*v[i].y + v[i].z*v[i].z + v[i].w*v[i].w;
    }
#pragma unroll
    for (int o = 16; o; o >>= 1) ss += __shfl_xor_sync(0xFFFFFFFFu, ss, o);
    if (lane == 0) sred[w] = ss;
    __syncthreads();
    float rs = rsqrtf((sred[0]+sred[1]+sred[2]+sred[3]) / (float)HDIM + 1e-6f);
    float4* outr = (float4*)(out + (size_t)t * HDIM);
    const float4* sc = (const float4*)ns;
    int mb = t >> 7, r = t & 127;
#pragma unroll
    for (int i = 0; i < 3; ++i) {
        int idx = tid + i * 128;
        float4 s4 = sc[idx], xv = v[i];
        outr[idx] = xv;
        float4 xn = make_float4(xv.x*rs*s4.x, xv.y*rs*s4.y, xv.z*rs*s4.z, xv.w*rs*s4.w);
        sxn[idx] = xn;
        int k0 = idx * 4, kb = k0 >> 6, c8 = (k0 & 63) >> 3;
        __half* dst = g_xn + ((size_t)(mb*24 + kb))*8192 + r*64 + ((c8 ^ (r & 7)) * 8) + (k0 & 7);
        *(uint2*)dst = make_uint2(h2u(__floats2half2_rn(xn.x, xn.y)),
                                  h2u(__floats2half2_rn(xn.z, xn.w)));
    }
    __syncthreads();
#pragma unroll
    for (int e = 0; e < 4; ++e) {
        const float4* ge = (const float4*)(gw + (size_t)(4*w + e) * HDIM);
        float d = 0.f;
#pragma unroll
        for (int i = 0; i < 12; ++i) {
            int idx = lane + i * 32;
            float4 a = sxn[idx], b = ge[idx];
            d += a.x*b.x + a.y*b.y + a.z*b.z + a.w*b.w;
        }
#pragma unroll
        for (int o = 16; o; o >>= 1) d += __shfl_xor_sync(0xFFFFFFFFu, d, o);
        if (lane == 0) slog[4*w + e] = d;
    }
    __syncthreads();
    if (tid == 0) {
        float vv[16]; unsigned used = 0; float tv[4]; int ti[4];
#pragma unroll
        for (int e = 0; e < 16; ++e) vv[e] = slog[e];
#pragma unroll
        for (int i = 0; i < 4; ++i) {
            float best = -1e30f; int bi = 0;
#pragma unroll
            for (int e = 0; e < 16; ++e)
                if (!((used>>e)&1u) && vv[e] > best) { best = vv[e]; bi = e; }
            used |= 1u << bi; tv[i] = best; ti[i] = bi;
        }
        float mx = tv[0], sum = 0.f, pr[4];
#pragma unroll
        for (int i = 0; i < 4; ++i) { pr[i] = expf(tv[i]-mx); sum += pr[i]; }
#pragma unroll
        for (int i = 0; i < 4; ++i) g_probs[t*4+i] = pr[i] / sum;
        if (t == 0) { for (int i = 0; i < 4; ++i) g_eids[i] = ti[i]; }
    }
}

// -------- convert: gather 4 experts, fp32->fp16, retile + swizzle ------------
// wu tile (nb<192, kb<24): 128 rows x 64 k (16KB); rows = 64 gate + 64 linear
//   of one 64-act-col group, interleaved by 8 (rr = (ar>>3)*16 + lin*8 + (ar&7)).
// wd tile (nb<12, kbg<192): 128 h-rows x 64 k (16KB).
__global__ void moe_convert(const float* __restrict__ wu, const float* __restrict__ wd,
                            const float* __restrict__ bu, const float* __restrict__ bd) {
    const int NU = I2*HDIM/8, ND = HDIM*IH/8, PER = NU + ND;
    const long long total = 4ll * PER;
    long long stride = (long long)gridDim.x * blockDim.x;
    for (long long i = (long long)blockIdx.x*blockDim.x + threadIdx.x; i < total; i += stride) {
        int slot = (int)(i / PER), r = (int)(i - (long long)slot * PER);
        int eid = g_eids[slot];
        const float4* src; __half* dst;
        if (r < NU) {
            int row = r / 192, k0 = (r % 192) * 8;
            src = (const float4*)(wu + (size_t)eid*I2*HDIM + (size_t)row*HDIM + k0);
            int lin = row >= IH, a = lin ? row - IH : row;
            int nb = slot*48 + (a >> 6), ar = a & 63;
            int rr = (ar >> 3) * 16 + (lin ? 8 : 0) + (ar & 7);
            int kb = k0 >> 6, c8 = (k0 & 63) >> 3;
            dst = g_wu + ((size_t)(nb*24 + kb))*8192 + rr*64 + ((c8 ^ (rr & 7)) * 8);
        } else {
            int r2 = r - NU;
            int row = r2 / 384, k0 = (r2 % 384) * 8;
            src = (const float4*)(wd + (size_t)eid*HDIM*IH + (size_t)row*IH + k0);
            int nb = row >> 7, rr = row & 127;
            int kbg = slot*48 + (k0 >> 6), c8 = (k0 & 63) >> 3;
            dst = g_wd + ((size_t)(nb*192 + kbg))*8192 + rr*64 + ((c8 ^ (rr & 7)) * 8);
        }
        float4 a = src[0], b = src[1];
        *(uint4*)dst = make_uint4(h2u(__floats2half2_rn(a.x,a.y)), h2u(__floats2half2_rn(a.z,a.w)),
                                  h2u(__floats2half2_rn(b.x,b.y)), h2u(__floats2half2_rn(b.z,b.w)));
    }
    int gt = blockIdx.x*blockDim.x + threadIdx.x;
    if (gt < 4*(I2+HDIM)) {
        int slot = gt/(I2+HDIM), j = gt%(I2+HDIM), eid = g_eids[slot];
        if (j < I2) g_bu[slot*I2+j] = bu[(size_t)eid*I2 + j];
        else        g_bd[slot*HDIM + (j-I2)] = bd[(size_t)eid*HDIM + (j-I2)];
    }
}

// ------- persistent GEMM: 128x128 x K(64/stage), 4 HMMA warps + 1 producer --
// 2 CTAs per SM (96KB smem, 160 threads each) for stall-independence.
// EPI 0 (up):  unit=(nb<192, mb<64), KSTEPS=24; SwiGLU*prob -> g_act
// EPI 1 (down):unit=(kc<3, nb<12, mb<64), KSTEPS=64; red.global.add into out
template <int KSTEPS, int EPI>
__global__ __launch_bounds__(160, 2) void gemm_tc(int ntiles, float* __restrict__ dout) {
    extern __shared__ char smem[];
    __shared__ __align__(8) unsigned long long mbar[2 * NSTG];
    uint32_t sb = smem_u32(smem);
    uint32_t mb0 = smem_u32(&mbar[0]);
    const int tid = threadIdx.x, lane = tid & 31, wid = tid >> 5;

    if (tid == 0) {
#pragma unroll
        for (int s = 0; s < NSTG; ++s) { MBAR_INIT(mb0 + 8*s, 1); MBAR_INIT(mb0 + 8*(NSTG+s), 4); }
        asm volatile("fence.proxy.async.shared::cta;" ::: "memory");
    }
    __syncthreads();

    if (wid == 4) {  // producer warp
        if (lane == 0) {
            int st = 0; uint32_t ph = 1;
            for (int tile = blockIdx.x; tile < ntiles; tile += gridDim.x) {
                int mb = tile & 63, rest = tile >> 6;
                int nb = EPI ? (rest % 12) : rest;
                int kc = EPI ? (rest / 12) : 0;
                const char* Ab = EPI
                    ? (const char*)g_act + ((size_t)mb*192 + kc*64) * 16384
                    : (const char*)g_xn  + ((size_t)mb*24) * 16384;
                const char* Bb = EPI
                    ? (const char*)g_wd + ((size_t)nb*192 + kc*64) * 16384
                    : (const char*)g_wu + ((size_t)nb*24) * 16384;
                for (int s = 0; s < KSTEPS; ++s) {
                    MBAR_WAIT(mb0 + 8*(NSTG+st), ph);
                    MBAR_EXPECT(mb0 + 8*st, STGB);
                    uint32_t sa = sb + st * STGB;
                    BULK(sa,         Ab + (size_t)s * 16384, 16384, mb0 + 8*st);
                    BULK(sa + 16384, Bb + (size_t)s * 16384, 16384, mb0 + 8*st);
                    if (++st == NSTG) { st = 0; ph ^= 1; }
                }
            }
        }
        return;
    }

    const int wm = (wid >> 1) * 64, wn = (wid & 1) * 64;
    int st = 0; uint32_t phF = 0;
    for (int tile = blockIdx.x; tile < ntiles; tile += gridDim.x) {
        int mb = tile & 63, rest = tile >> 6;
        int nb = EPI ? (rest % 12) : rest;
        int kc = EPI ? (rest / 12) : 0;
        float acc[4][8][4];
#pragma unroll
        for (int i = 0; i < 4; ++i)
#pragma unroll
            for (int j = 0; j < 8; ++j)
#pragma unroll
                for (int q = 0; q < 4; ++q) acc[i][j][q] = 0.f;

        for (int s = 0; s < KSTEPS; ++s) {
            MBAR_WAIT(mb0 + 8*st, phF);
            uint32_t sA = sb + st * STGB, sB = sA + 16384;
#pragma unroll
            for (int ks = 0; ks < 4; ++ks) {
                uint32_t a[4][4], b[8][2];
#pragma unroll
                for (int i = 0; i < 4; ++i) {
                    int ro = wm + i*16 + (lane & 15), ko = ks*16 + ((lane >> 4) << 3);
                    LDSM4(a[i][0],a[i][1],a[i][2],a[i][3],
                          sA + ro*128 + ((((ko >> 3) ^ (ro & 7))) << 4));
                }
#pragma unroll
                for (int j = 0; j < 8; j += 2) {
                    int grp = lane >> 3;
                    int ro = wn + (j + (grp >> 1))*8 + (lane & 7);
                    int ko = ks*16 + ((grp & 1) << 3);
                    LDSM4(b[j][0],b[j][1],b[j+1][0],b[j+1][1],
                          sB + ro*128 + ((((ko >> 3) ^ (ro & 7))) << 4));
                }
#pragma unroll
                for (int i = 0; i < 4; ++i)
#pragma unroll
                    for (int j = 0; j < 8; ++j) MMA(acc[i][j], a[i], b[j]);
            }
            if (lane == 0) MBAR_ARRIVE(mb0 + 8*(NSTG + st));
            if (++st == NSTG) { st = 0; phF ^= 1; }
        }

        if (EPI == 0) {
            int slot = nb / 48, nbl = nb - slot * 48;   // 64 act cols per tile
            const float* bug = g_bu + slot*I2 + nbl*64;
            const float* bul = bug + IH;
#pragma unroll
            for (int i = 0; i < 4; ++i) {
                int r = wm + i*16 + (lane >> 2);
                float p0 = g_probs[(mb*128 + r)*4 + slot];
                float p1 = g_probs[(mb*128 + r + 8)*4 + slot];
#pragma unroll
                for (int t = 0; t < 4; ++t) {
                    int ac = (wn >> 1) + t*8 + (lane & 3) * 2;   // [0,64)
                    float bg0 = bug[ac], bg1 = bug[ac+1], bl0 = bul[ac], bl1 = bul[ac+1];
#pragma unroll
                    for (int h = 0; h < 2; ++h) {
                        int tr = r + h*8;
                        float pp = h ? p1 : p0;
                        float gg0 = acc[i][2*t][2*h]   + bg0, gg1 = acc[i][2*t][2*h+1]   + bg1;
                        float ll0 = acc[i][2*t+1][2*h] + bl0, ll1 = acc[i][2*t+1][2*h+1] + bl1;
                        gg0 = fminf(gg0, LIMIT); gg1 = fminf(gg1, LIMIT);
                        ll0 = fminf(fmaxf(ll0, -LIMIT), LIMIT);
                        ll1 = fminf(fmaxf(ll1, -LIMIT), LIMIT);
                        float a0 = pp * (gg0 / (1.f + __expf(-ALPHA*gg0)) * (ll0 + 1.f));
                        float a1 = pp * (gg1 / (1.f + __expf(-ALPHA*gg1)) * (ll1 + 1.f));
                        int ag = nb*64 + ac;   // global act col (incl. slot)
                        __half* dst = g_act + ((size_t)(mb*192 + (ag >> 6)))*8192
                            + tr*64 + ((((ag & 63) >> 3) ^ (tr & 7)) * 8) + (ac & 7);
                        *(__half2*)dst = __floats2half2_rn(a0, a1);
                    }
                }
            }
        } else {
#pragma unroll
            for (int i = 0; i < 4; ++i) {
                int r = wm + i*16 + (lane >> 2);
                int t0 = mb*128 + r;
                float4 P0 = *(const float4*)&g_probs[t0*4];
                float4 P1 = *(const float4*)&g_probs[(t0+8)*4];
                float* o0 = dout + (size_t)t0*HDIM + nb*128;
                float* o1 = o0 + 8ull*HDIM;
#pragma unroll
                for (int j = 0; j < 8; ++j) {
                    int c = wn + j*8 + (lane & 3) * 2;   // [0,128)
                    int cg = nb*128 + c;
#pragma unroll
                    for (int q = 0; q < 2; ++q) {
                        float bs0 = 0.f, bs1 = 0.f;
                        if (kc == 0) {
                            float bd0 = g_bd[cg+q], bd1 = g_bd[HDIM+cg+q],
                                  bd2 = g_bd[2*HDIM+cg+q], bd3 = g_bd[3*HDIM+cg+q];
                            bs0 = P0.x*bd0 + P0.y*bd1 + P0.z*bd2 + P0.w*bd3;
                            bs1 = P1.x*bd0 + P1.y*bd1 + P1.z*bd2 + P1.w*bd3;
                        }
                        REDADD(o0 + c + q, acc[i][j][q]   + bs0);
                        REDADD(o1 + c + q, acc[i][j][2+q] + bs1);
                    }
                }
            }
        }
    }
}

// ---------------- host ----------------
extern "C" void kernel_launch(void* const* d_in, const int* in_sizes, int n_in,
                              void* d_out, int out_size) {
    const float* x  = (const float*)d_in[0];
    const float* ns = (const float*)d_in[1];
    const float* gw = (const float*)d_in[2];
    const float* wu = (const float*)d_in[3];
    const float* bu = (const float*)d_in[4];
    const float* wd = (const float*)d_in[5];
    const float* bd = (const float*)d_in[6];
    float* out = (float*)d_out;

    int sms = 148;
    cudaDeviceGetAttribute(&sms, cudaDevAttrMultiProcessorCount, 0);

    cudaFuncSetAttribute(gemm_tc<24, 0>, cudaFuncAttributeMaxDynamicSharedMemorySize, SMEMSZ);
    cudaFuncSetAttribute(gemm_tc<64, 1>, cudaFuncAttributeMaxDynamicSharedMemorySize, SMEMSZ);

    moe_prep<<<T_TOK, 128>>>(x, ns, gw, out);
    moe_convert<<<1024, 256>>>(wu, wd, bu, bd);
    gemm_tc<24, 0><<<2*sms, 160, SMEMSZ>>>(192 * 64, nullptr);     // all 4 up-GEMMs
    gemm_tc<64, 1><<<2*sms, 160, SMEMSZ>>>(3 * 12 * 64, out);      // down, K-split x3
}